// round 10
// baseline (speedup 1.0000x reference)
#include <cuda_runtime.h>
#include <cuda_fp16.h>
#include <cuda_pipeline.h>

// SAG: CSR SpMM neighbor aggregation, deg=16, D=48, fp32 in/out.
//
// R9: R7 was latency-bound with every unit <55% busy: in-flight gather data
// lives in registers, so occ x MLP is pinned by RF size (~480 outstanding
// loads/SM, not enough for loaded-L2 latency). Fix: stage gathers with
// cp.async (LDGSTS) into shared memory -- no destination register, so each
// warp keeps 16 copies in flight at zero RF cost (>1000 outstanding/SM).
// Each lane stages and later consumes ONLY its own bytes, so a per-thread
// __pipeline_wait_prior(0) suffices (no block sync). fp16 two-tree
// accumulation kept (rel_err ~5e-4). Expect the ~180MB LTS byte floor
// (~12.4us) to finally bind: main ~13-14us.

#define N_CAP    100000
#define D_FEAT   48
#define ROW_B    96           // fp16 row bytes
#define NODE_SLOT (16 * ROW_B)   // 1536 B staged per node (16 edges)

__device__ __align__(16) __half2 g_Xh[(size_t)N_CAP * 24];   // 9.6 MB scratch

// ---- pre-pass: fp32 [n,48] -> fp16 [n,48] (contiguous, vectorized) ---------
__global__ void convert_kernel(const float4* __restrict__ X4, int total4)
{
    int t = blockIdx.x * blockDim.x + threadIdx.x;   // one float4 -> one uint2
    if (t >= total4) return;
    const float4 f = __ldg(X4 + t);
    const __half2 a = __floats2half2_rn(f.x, f.y);
    const __half2 b = __floats2half2_rn(f.z, f.w);
    uint2 v;
    v.x = *reinterpret_cast<const unsigned int*>(&a);
    v.y = *reinterpret_cast<const unsigned int*>(&b);
    reinterpret_cast<uint2*>(g_Xh)[t] = v;
}

// ---- main: 2 nodes/warp, cp.async-staged gather, fp16 two-tree sum ---------
__global__ __launch_bounds__(256, 8)
void sag_fp16_kernel(const int* __restrict__ row_pointers,
                     const int* __restrict__ column_index,
                     float* __restrict__ out,
                     int n_nodes)
{
    // 16 nodes per 256-thread block, 1536 B staged per node = 24576 B.
    __shared__ __align__(16) char stage[16 * NODE_SLOT];

    const int sub  = threadIdx.x & 15;                  // lane within node group
    const int nib  = threadIdx.x >> 4;                  // node index in block
    const int node = blockIdx.x * 16 + nib;
    if (node >= n_nodes) return;

    const int base = row_pointers[node];
    const int deg  = row_pointers[node + 1] - base;

    // sub-lane e holds edge e's neighbor index (coalesced)
    int my_idx = 0;
    if (sub < deg) my_idx = column_index[base + sub];

    // Lanes 12-15 duplicate lane 11 (src AND dst): same value written to the
    // same smem address -- benign, keeps everything branch-free.
    const int subc   = (sub < 12) ? sub : 11;
    const int lane_b = subc * 8;                        // byte offset in row
    const char* __restrict__ Xb = reinterpret_cast<const char*>(g_Xh);
    char* const my_slot = stage + nib * NODE_SLOT;

    if (deg == 16) {
        // Stage all 16 rows via cp.async: 16 in-flight copies per thread,
        // zero register cost.
        #pragma unroll
        for (int e = 0; e < 16; ++e) {
            const int idx = __shfl_sync(0xffffffffu, my_idx, e, 16);
            __pipeline_memcpy_async(my_slot + e * ROW_B + lane_b,
                                    Xb + idx * ROW_B + lane_b, 8);
        }
        __pipeline_commit();
        __pipeline_wait_prior(0);   // this thread's copies have landed

        // Two independent fp16 trees (edges 0-7, 8-15) combined in fp32.
        __half2 t0a = __float2half2_rn(0.f), t0b = __float2half2_rn(0.f);
        __half2 t1a = __float2half2_rn(0.f), t1b = __float2half2_rn(0.f);

        #pragma unroll
        for (int e = 0; e < 16; ++e) {
            const int2 v = *reinterpret_cast<const int2*>(my_slot + e * ROW_B + lane_b);
            const __half2 h0 = *reinterpret_cast<const __half2*>(&v.x);
            const __half2 h1 = *reinterpret_cast<const __half2*>(&v.y);
            if (e < 8) { t0a = __hadd2(t0a, h0); t0b = __hadd2(t0b, h1); }
            else       { t1a = __hadd2(t1a, h0); t1b = __hadd2(t1b, h1); }
        }

        if (sub < 12) {
            const float2 f0 = __half22float2(t0a);
            const float2 f1 = __half22float2(t0b);
            const float2 g0 = __half22float2(t1a);
            const float2 g1 = __half22float2(t1b);
            reinterpret_cast<float4*>(out)[node * 12 + sub] =
                make_float4(f0.x + g0.x, f0.y + g0.y, f1.x + g1.x, f1.y + g1.y);
        }
    } else {
        // Generic fallback (never taken here): direct fp32 accumulate.
        float a0 = 0.f, a1 = 0.f, a2 = 0.f, a3 = 0.f;
        for (int e = 0; e < deg; ++e) {
            int idx = (e < 16) ? __shfl_sync(0xffffffffu, my_idx, e, 16)
                               : column_index[base + e];
            const int2 v = *reinterpret_cast<const int2*>(Xb + idx * ROW_B + lane_b);
            const float2 f0 = __half22float2(*reinterpret_cast<const __half2*>(&v.x));
            const float2 f1 = __half22float2(*reinterpret_cast<const __half2*>(&v.y));
            a0 += f0.x; a1 += f0.y; a2 += f1.x; a3 += f1.y;
        }
        if (sub < 12) {
            reinterpret_cast<float4*>(out)[node * 12 + sub] =
                make_float4(a0, a1, a2, a3);
        }
    }
}

// ---- fp32 fallback (only if n exceeds scratch capacity) --------------------
__global__ __launch_bounds__(256, 8)
void sag_fp32_kernel(const float* __restrict__ X,
                     const int* __restrict__ row_pointers,
                     const int* __restrict__ column_index,
                     float* __restrict__ out,
                     int n_nodes)
{
    const int tid  = blockIdx.x * blockDim.x + threadIdx.x;
    const int node = tid >> 4;
    const int lane = tid & 15;
    if (node >= n_nodes) return;

    const int base = row_pointers[node];
    const int deg  = row_pointers[node + 1] - base;
    int my_idx = 0;
    if (lane < deg) my_idx = column_index[base + lane];

    float a0 = 0.f, a1 = 0.f, a2 = 0.f;
    for (int e = 0; e < deg; ++e) {
        int idx = (e < 16) ? __shfl_sync(0xffffffffu, my_idx, e, 16)
                           : column_index[base + e];
        const float* row = X + (size_t)idx * D_FEAT;
        a0 += __ldg(row + lane);
        a1 += __ldg(row + lane + 16);
        a2 += __ldg(row + lane + 32);
    }
    float* orow = out + (size_t)node * D_FEAT;
    orow[lane] = a0; orow[lane + 16] = a1; orow[lane + 32] = a2;
}

extern "C" void kernel_launch(void* const* d_in, const int* in_sizes, int n_in,
                              void* d_out, int out_size)
{
    const float* X   = (const float*)d_in[0];
    const int*   rp  = (const int*)d_in[1];
    const int*   col = (const int*)d_in[2];
    float*       out = (float*)d_out;

    const int n_nodes = in_sizes[1] - 1;

    if (n_nodes <= N_CAP) {
        {
            const int total4 = n_nodes * (D_FEAT / 4);      // 1.2M float4
            const int threads = 256;
            convert_kernel<<<(total4 + threads - 1) / threads, threads>>>(
                reinterpret_cast<const float4*>(X), total4);
        }
        {
            const int threads = 256;                         // 16 nodes / block
            const int blocks = (n_nodes + 15) / 16;
            sag_fp16_kernel<<<blocks, threads>>>(rp, col, out, n_nodes);
        }
    } else {
        const int threads = 256;
        const int blocks = (n_nodes * 16 + threads - 1) / threads;
        sag_fp32_kernel<<<blocks, threads>>>(X, rp, col, out, n_nodes);
    }
}

// round 11
// speedup vs baseline: 3.3480x; 3.3480x over previous
#include <cuda_runtime.h>
#include <cuda_fp16.h>

// SAG: CSR SpMM neighbor aggregation, deg=16, D=48, fp32 in/out.
//
// R10: R7 was bound by L1tex within-LDG replays (2.07 cyc/wf): unaligned 96B
// fp16 rows straddle ~1.75 cache lines, ~56 gather wavefronts/warp = ~116
// cyc/warp = the measured 19.6us. Fix: pad fp16 rows to 128B so each row is
// exactly ONE aligned line -> 2 wavefronts per LDG.64 (32/warp), wavefront
// cost drops below the LTS byte floor. L2 sector traffic is unchanged
// (32B sectors: only the 3 used sectors of each line are fetched), so the
// ~180MB / ~12.9TB/s LTS floor (~14us) becomes the binder. Addressing is now
// idx<<4 (shift, no IMAD). Everything else identical to R7 (branch-free
// clamp, fp16 two-tree accumulation rel_err ~5e-4, launch_bounds(256,8)).

#define N_CAP   100000
#define D_FEAT  48
#define ROW_I2  16            // padded row: 128 B = 16 int2 (4 halves each)
#define USED_I2 12            // 96 B real data

__device__ __align__(128) __half2 g_Xh[(size_t)N_CAP * 32];   // 12.8 MB scratch

// ---- pre-pass: fp32 [n,48] -> fp16 [n,64pad] (one thread per int2 slot) ----
__global__ void convert_kernel(const float2* __restrict__ X2, int n_nodes)
{
    int t = blockIdx.x * blockDim.x + threadIdx.x;   // one uint2 out slot
    const int total = n_nodes * ROW_I2;
    if (t >= total) return;
    const int row = t >> 4;           // /16
    const int c   = t & 15;
    uint2 v = make_uint2(0u, 0u);
    if (c < USED_I2) {
        // input row = 24 float2; slot c covers float2 pair {2c, 2c+1}
        const float2 f0 = __ldg(X2 + row * 24 + 2 * c);
        const float2 f1 = __ldg(X2 + row * 24 + 2 * c + 1);
        const __half2 a = __floats2half2_rn(f0.x, f0.y);
        const __half2 b = __floats2half2_rn(f1.x, f1.y);
        v.x = *reinterpret_cast<const unsigned int*>(&a);
        v.y = *reinterpret_cast<const unsigned int*>(&b);
    }
    reinterpret_cast<uint2*>(g_Xh)[t] = v;
}

// ---- main: 2 nodes/warp, 16 lanes/node, branch-free fp16 two-tree sum ------
__global__ __launch_bounds__(256, 8)
void sag_fp16_kernel(const int* __restrict__ row_pointers,
                     const int* __restrict__ column_index,
                     float* __restrict__ out,
                     int n_nodes)
{
    const int sub  = threadIdx.x & 15;                  // lane within node group
    const int node = ((blockIdx.x * blockDim.x + threadIdx.x) >> 4);
    if (node >= n_nodes) return;

    const int base = row_pointers[node];
    const int deg  = row_pointers[node + 1] - base;

    // sub-lane e holds edge e's neighbor index (coalesced)
    int my_idx = 0;
    if (sub < deg) my_idx = column_index[base + sub];

    // Lanes 12-15 duplicate lane 11's slot: same line, zero extra traffic,
    // results discarded at store time. Keeps the loop branch-free.
    const int subc = (sub < USED_I2) ? sub : (USED_I2 - 1);
    const int2* __restrict__ Xi2 = reinterpret_cast<const int2*>(g_Xh);

    if (deg == 16) {
        // Two independent fp16 trees (edges 0-7, 8-15) combined in fp32.
        __half2 t0a = __float2half2_rn(0.f), t0b = __float2half2_rn(0.f);
        __half2 t1a = __float2half2_rn(0.f), t1b = __float2half2_rn(0.f);

        #pragma unroll
        for (int e = 0; e < 16; ++e) {
            const int idx = __shfl_sync(0xffffffffu, my_idx, e, 16);
            const int2 v = __ldg(Xi2 + ((idx << 4) + subc));   // shift, no IMAD
            const __half2 h0 = *reinterpret_cast<const __half2*>(&v.x);
            const __half2 h1 = *reinterpret_cast<const __half2*>(&v.y);
            if (e < 8) { t0a = __hadd2(t0a, h0); t0b = __hadd2(t0b, h1); }
            else       { t1a = __hadd2(t1a, h0); t1b = __hadd2(t1b, h1); }
        }

        if (sub < USED_I2) {
            const float2 f0 = __half22float2(t0a);
            const float2 f1 = __half22float2(t0b);
            const float2 g0 = __half22float2(t1a);
            const float2 g1 = __half22float2(t1b);
            reinterpret_cast<float4*>(out)[node * USED_I2 + sub] =
                make_float4(f0.x + g0.x, f0.y + g0.y, f1.x + g1.x, f1.y + g1.y);
        }
    } else {
        // Generic fallback (never taken here): fp32 accumulate.
        float a0 = 0.f, a1 = 0.f, a2 = 0.f, a3 = 0.f;
        for (int e = 0; e < deg; ++e) {
            int idx = (e < 16) ? __shfl_sync(0xffffffffu, my_idx, e, 16)
                               : column_index[base + e];
            const int2 v = __ldg(Xi2 + ((idx << 4) + subc));
            const float2 f0 = __half22float2(*reinterpret_cast<const __half2*>(&v.x));
            const float2 f1 = __half22float2(*reinterpret_cast<const __half2*>(&v.y));
            a0 += f0.x; a1 += f0.y; a2 += f1.x; a3 += f1.y;
        }
        if (sub < USED_I2) {
            reinterpret_cast<float4*>(out)[node * USED_I2 + sub] =
                make_float4(a0, a1, a2, a3);
        }
    }
}

// ---- fp32 fallback (only if n exceeds scratch capacity) --------------------
__global__ __launch_bounds__(256, 8)
void sag_fp32_kernel(const float* __restrict__ X,
                     const int* __restrict__ row_pointers,
                     const int* __restrict__ column_index,
                     float* __restrict__ out,
                     int n_nodes)
{
    const int tid  = blockIdx.x * blockDim.x + threadIdx.x;
    const int node = tid >> 4;
    const int lane = tid & 15;
    if (node >= n_nodes) return;

    const int base = row_pointers[node];
    const int deg  = row_pointers[node + 1] - base;
    int my_idx = 0;
    if (lane < deg) my_idx = column_index[base + lane];

    float a0 = 0.f, a1 = 0.f, a2 = 0.f;
    for (int e = 0; e < deg; ++e) {
        int idx = (e < 16) ? __shfl_sync(0xffffffffu, my_idx, e, 16)
                           : column_index[base + e];
        const float* row = X + (size_t)idx * D_FEAT;
        a0 += __ldg(row + lane);
        a1 += __ldg(row + lane + 16);
        a2 += __ldg(row + lane + 32);
    }
    float* orow = out + (size_t)node * D_FEAT;
    orow[lane] = a0; orow[lane + 16] = a1; orow[lane + 32] = a2;
}

extern "C" void kernel_launch(void* const* d_in, const int* in_sizes, int n_in,
                              void* d_out, int out_size)
{
    const float* X   = (const float*)d_in[0];
    const int*   rp  = (const int*)d_in[1];
    const int*   col = (const int*)d_in[2];
    float*       out = (float*)d_out;

    const int n_nodes = in_sizes[1] - 1;

    if (n_nodes <= N_CAP) {
        {
            const int total = n_nodes * ROW_I2;              // 1.6M slots
            const int threads = 256;
            convert_kernel<<<(total + threads - 1) / threads, threads>>>(
                reinterpret_cast<const float2*>(X), n_nodes);
        }
        {
            const int threads = 256;                         // 16 nodes / block
            const int blocks = (n_nodes + 15) / 16;
            sag_fp16_kernel<<<blocks, threads>>>(rp, col, out, n_nodes);
        }
    } else {
        const int threads = 256;
        const int blocks = (n_nodes * 16 + threads - 1) / threads;
        sag_fp32_kernel<<<blocks, threads>>>(X, rp, col, out, n_nodes);
    }
}